// round 3
// baseline (speedup 1.0000x reference)
#include <cuda_runtime.h>
#include <cstdint>

// Problem shape (fixed for this problem instance)
#define M_TOK 65536   // B*N = 32*2048
#define C_DIM 1024
#define H_DIM 512     // C/2
#define Q_DIM 256     // C/4

// ---------------- scratch (device globals: sanctioned alloc workaround) ---
__device__ float g_mu[M_TOK];
__device__ float g_rstd[M_TOK];
__device__ float g_bias2[H_DIM];
__device__ float g_h1[(size_t)M_TOK * H_DIM];   // 128 MiB
__device__ float g_h2[(size_t)M_TOK * H_DIM];   // 128 MiB
__device__ float g_h3[(size_t)M_TOK * Q_DIM];   //  64 MiB

// ---------------- helpers -------------------------------------------------
__device__ __forceinline__ float gelu_f(float v) {
    // exact gelu: x * 0.5 * (1 + erf(x / sqrt(2)))
    return 0.5f * v * (1.0f + erff(v * 0.70710678118654752440f));
}

__device__ __forceinline__ void fma2(unsigned long long& d,
                                     unsigned long long a,
                                     unsigned long long b) {
    // packed 2-lane fp32 FMA, per-lane round-to-nearest (bit-identical to 2x fmaf)
    asm("fma.rn.f32x2 %0, %1, %2, %0;" : "+l"(d) : "l"(a), "l"(b));
}
__device__ __forceinline__ void unpack2(unsigned long long v, float& lo, float& hi) {
    asm("mov.b64 {%0, %1}, %2;" : "=f"(lo), "=f"(hi) : "l"(v));
}

// ---------------- LN row statistics ---------------------------------------
__global__ __launch_bounds__(256)
void ln_stats_kernel(const float* __restrict__ x) {
    int row  = (blockIdx.x * 256 + threadIdx.x) >> 5;
    int lane = threadIdx.x & 31;
    const float4* xr = (const float4*)(x + (size_t)row * C_DIM);
    float s = 0.f, ss = 0.f;
#pragma unroll
    for (int i = 0; i < C_DIM / 128; ++i) {
        float4 v = xr[lane + 32 * i];
        s  += v.x + v.y + v.z + v.w;
        ss += v.x * v.x + v.y * v.y + v.z * v.z + v.w * v.w;
    }
#pragma unroll
    for (int o = 16; o; o >>= 1) {
        s  += __shfl_xor_sync(0xffffffffu, s,  o);
        ss += __shfl_xor_sync(0xffffffffu, ss, o);
    }
    if (lane == 0) {
        float mu  = s  * (1.0f / C_DIM);
        float var = ss * (1.0f / C_DIM) - mu * mu;
        g_mu[row]   = mu;
        g_rstd[row] = rsqrtf(var + 1e-5f);
    }
}

// ---------------- bias2 = noise_feature @ W_l1[512:1024, :] ---------------
__global__ void bias2_kernel(const float* __restrict__ nf,
                             const float* __restrict__ Wl1) {
    int j = blockIdx.x * blockDim.x + threadIdx.x;   // 0..511
    const float* wp = Wl1 + (size_t)H_DIM * H_DIM + j;  // row 512, col j
    float s = 0.f;
    for (int k = 0; k < H_DIM; ++k)
        s += nf[k] * wp[(size_t)k * H_DIM];
    g_bias2[j] = s;
}

// ---------------- tiled fp32 GEMM (BM=128, BN=128, BK=16), f32x2 FMAs -----
// MODE 0: C = gelu(LN(x) @ W_L)            A = x (param), C = g_h1, K=1024
// MODE 1: C = gelu(g_h1 @ W_l1_top + b2)   A = g_h1,      C = g_h2, K=512
// MODE 2: C = gelu(g_h2 @ W_l2)            A = g_h2,      C = g_h3, K=512, N=256
template <int MODE>
__global__ __launch_bounds__(256)
void gemm_kernel(const float* __restrict__ Ain, const float* __restrict__ Bm,
                 const float* __restrict__ lnscale, const float* __restrict__ lnbias) {
    constexpr int K  = (MODE == 0) ? C_DIM : H_DIM;
    constexpr int Nn = (MODE == 2) ? Q_DIM : H_DIM;
    constexpr int KT = K / 16;

    const float* A = (MODE == 0) ? Ain : (MODE == 1 ? g_h1 : g_h2);
    float* Cm      = (MODE == 0) ? g_h1 : (MODE == 1 ? g_h2 : g_h3);

    __shared__ float As[2][16][132];   // transposed A tile (+4 pad)
    __shared__ float Bs[2][16][128];
    __shared__ float sMu[128], sRstd[128];

    const int tid = threadIdx.x;
    const int tx = tid & 15, ty = tid >> 4;
    const int m0 = blockIdx.y * 128;
    const int n0 = blockIdx.x * 128;

    if (MODE == 0 && tid < 128) {
        sMu[tid]   = g_mu[m0 + tid];
        sRstd[tid] = g_rstd[m0 + tid];
    }

    // staging index maps
    const int ar = tid >> 2;          // 0..63  (A rows ar, ar+64)
    const int ac = (tid & 3) << 2;    // 0,4,8,12
    const int br = tid >> 5;          // 0..7   (B rows br, br+8)
    const int bc = (tid & 31) << 2;

    const float* aPtr = A  + (size_t)(m0 + ar) * K + ac;
    const float* bPtr = Bm + (size_t)br * Nn + n0 + bc;

    unsigned long long acc[8][4];
#pragma unroll
    for (int m = 0; m < 8; ++m)
#pragma unroll
        for (int j = 0; j < 4; ++j) acc[m][j] = 0ull;

    float4 aR[2], bR[2];

    auto stage = [&](int kt, int b) {
#pragma unroll
        for (int h = 0; h < 2; ++h) {
            int row  = ar + h * 64;
            float4 v = aR[h];
            if (MODE == 0) {
                float mu = sMu[row], rs = sRstd[row];
                int k = kt * 16 + ac;
                v.x = (v.x - mu) * rs * lnscale[k + 0] + lnbias[k + 0];
                v.y = (v.y - mu) * rs * lnscale[k + 1] + lnbias[k + 1];
                v.z = (v.z - mu) * rs * lnscale[k + 2] + lnbias[k + 2];
                v.w = (v.w - mu) * rs * lnscale[k + 3] + lnbias[k + 3];
            }
            As[b][ac + 0][row] = v.x;
            As[b][ac + 1][row] = v.y;
            As[b][ac + 2][row] = v.z;
            As[b][ac + 3][row] = v.w;
        }
        *(float4*)&Bs[b][br    ][bc] = bR[0];
        *(float4*)&Bs[b][br + 8][bc] = bR[1];
    };

    // tile 0
    aR[0] = *(const float4*)(aPtr);
    aR[1] = *(const float4*)(aPtr + (size_t)64 * K);
    bR[0] = *(const float4*)(bPtr);
    bR[1] = *(const float4*)(bPtr + (size_t)8 * Nn);
    __syncthreads();                 // sMu/sRstd visible
    stage(0, 0);
    __syncthreads();

    int buf = 0;
    for (int kt = 0; kt < KT; ++kt) {
        if (kt + 1 < KT) {
            const float* ap = aPtr + (kt + 1) * 16;
            aR[0] = *(const float4*)ap;
            aR[1] = *(const float4*)(ap + (size_t)64 * K);
            const float* bp = bPtr + (size_t)(kt + 1) * 16 * Nn;
            bR[0] = *(const float4*)bp;
            bR[1] = *(const float4*)(bp + (size_t)8 * Nn);
        }
#pragma unroll
        for (int kk = 0; kk < 16; ++kk) {
            const float4 a0 = *(const float4*)&As[buf][kk][ty * 8];
            const float4 a1 = *(const float4*)&As[buf][kk][ty * 8 + 4];
            const unsigned long long* bp2 =
                (const unsigned long long*)&Bs[buf][kk][tx * 8];
            unsigned long long b0 = bp2[0], b1 = bp2[1], b2 = bp2[2], b3 = bp2[3];
            float av[8] = {a0.x, a0.y, a0.z, a0.w, a1.x, a1.y, a1.z, a1.w};
#pragma unroll
            for (int m = 0; m < 8; ++m) {
                unsigned long long a2;
                asm("mov.b64 %0, {%1, %1};" : "=l"(a2) : "f"(av[m]));
                fma2(acc[m][0], a2, b0);
                fma2(acc[m][1], a2, b1);
                fma2(acc[m][2], a2, b2);
                fma2(acc[m][3], a2, b3);
            }
        }
        if (kt + 1 < KT) stage(kt + 1, buf ^ 1);
        __syncthreads();
        buf ^= 1;
    }

    // epilogue: (optional bias) + gelu, vectorized stores
#pragma unroll
    for (int m = 0; m < 8; ++m) {
        int row = m0 + ty * 8 + m;
        float* cp = Cm + (size_t)row * Nn + n0 + tx * 8;
        float o[8];
#pragma unroll
        for (int j = 0; j < 4; ++j) {
            float lo, hi;
            unpack2(acc[m][j], lo, hi);
            if (MODE == 1) {
                int col = n0 + tx * 8 + 2 * j;
                lo += g_bias2[col];
                hi += g_bias2[col + 1];
            }
            o[2 * j]     = gelu_f(lo);
            o[2 * j + 1] = gelu_f(hi);
        }
        *(float4*)(cp)     = make_float4(o[0], o[1], o[2], o[3]);
        *(float4*)(cp + 4) = make_float4(o[4], o[5], o[6], o[7]);
    }
}

// ---------------- final: logit, sigmoid, STE mask, gated output -----------
__global__ __launch_bounds__(256)
void final_kernel(const float* __restrict__ x, const float* __restrict__ prevm,
                  const float* __restrict__ w3, float* __restrict__ out,
                  int write_extra) {
    int row  = (blockIdx.x * 256 + threadIdx.x) >> 5;
    int lane = threadIdx.x & 31;
    const float* h3 = g_h3 + (size_t)row * Q_DIM;
    float s = 0.f;
#pragma unroll
    for (int i = 0; i < 8; ++i) s += h3[lane + 32 * i] * w3[lane + 32 * i];
#pragma unroll
    for (int o = 16; o; o >>= 1) s += __shfl_xor_sync(0xffffffffu, s, o);

    float prob = 1.0f / (1.0f + expf(-s));
    float xm   = prob * prevm[row];
    float m    = (xm > 0.5f) ? 1.0f : 0.0f;

    if (lane == 0 && write_extra) {
        out[(size_t)M_TOK * C_DIM + row]         = m;                     // mask
        out[(size_t)M_TOK * C_DIM + M_TOK + row] = (m > 0.f) ? 1.0f       // curr_m+1e-10
                                                             : 1e-10f;
    }
    const float4* xr = (const float4*)(x + (size_t)row * C_DIM);
    float4* orow     = (float4*)(out + (size_t)row * C_DIM);
#pragma unroll
    for (int i = 0; i < 8; ++i) {
        float4 v = xr[lane + 32 * i];
        v.x *= m; v.y *= m; v.z *= m; v.w *= m;
        orow[lane + 32 * i] = v;
    }
}

// ---------------- launch ---------------------------------------------------
extern "C" void kernel_launch(void* const* d_in, const int* in_sizes, int n_in,
                              void* d_out, int out_size) {
    const float* x   = (const float*)d_in[0];   // input_feature [32,2048,1024]
    const float* nf  = (const float*)d_in[1];   // noise_feature [1,1,512]
    const float* pm  = (const float*)d_in[2];   // prev_m [32,2048]
    const float* lns = (const float*)d_in[3];   // ln_scale [1024]
    const float* lnb = (const float*)d_in[4];   // ln_bias [1024]
    const float* WL  = (const float*)d_in[5];   // [1024,512]
    const float* Wl1 = (const float*)d_in[6];   // [1024,512]
    const float* Wl2 = (const float*)d_in[7];   // [512,256]
    const float* W3  = (const float*)d_in[8];   // [256,1]
    float* out = (float*)d_out;

    ln_stats_kernel<<<M_TOK / 8, 256>>>(x);
    bias2_kernel<<<2, 256>>>(nf, Wl1);
    gemm_kernel<0><<<dim3(H_DIM / 128, M_TOK / 128), 256>>>(x, WL, lns, lnb);
    gemm_kernel<1><<<dim3(H_DIM / 128, M_TOK / 128), 256>>>(nullptr, Wl1, nullptr, nullptr);
    gemm_kernel<2><<<dim3(Q_DIM / 128, M_TOK / 128), 256>>>(nullptr, Wl2, nullptr, nullptr);

    int extra = (out_size >= M_TOK * C_DIM + 2 * M_TOK) ? 1 : 0;
    final_kernel<<<M_TOK / 8, 256>>>(x, pm, W3, out, extra);
}